// round 2
// baseline (speedup 1.0000x reference)
#include <cuda_runtime.h>
#include <cstdint>

#define BDIM 64
#define TDIM 2048
#define DDIM 256
#define HDIM 256
#define G3   768

// Scratch for the input projection xg = x @ W_ih^T + b_ih : [B*T, 3H] fp32
__device__ float g_xg[(size_t)BDIM * TDIM * G3];

// ---------------- f32x2 helpers (Blackwell packed fp32) ----------------
__device__ __forceinline__ unsigned long long pk2(float x, float y) {
    unsigned long long r;
    asm("mov.b64 %0, {%1, %2};" : "=l"(r) : "f"(x), "f"(y));
    return r;
}
__device__ __forceinline__ void upk2(unsigned long long p, float& x, float& y) {
    asm("mov.b64 {%0, %1}, %2;" : "=f"(x), "=f"(y) : "l"(p));
}
__device__ __forceinline__ unsigned long long fma2(unsigned long long a,
                                                   unsigned long long b,
                                                   unsigned long long c) {
    unsigned long long d;
    asm("fma.rn.f32x2 %0, %1, %2, %3;" : "=l"(d) : "l"(a), "l"(b), "l"(c));
    return d;
}

// ---------------- Kernel 1: projection GEMM (unchanged from R1) ----------------
#define BM 64
#define BN 64
#define BK 32

__global__ __launch_bounds__(256) void proj_gemm(const float* __restrict__ x,
                                                 const float* __restrict__ W,
                                                 const float* __restrict__ bias) {
    __shared__ float As[BK][BM + 4];
    __shared__ float Bs[BK][BN + 4];
    const int tid = threadIdx.x;
    const int gm = blockIdx.x * BM;
    const int gn = blockIdx.y * BN;
    const int m4 = (tid >> 4) * 4;
    const int n4 = (tid & 15) * 4;

    unsigned long long acc[4][2];
#pragma unroll
    for (int i = 0; i < 4; i++) { acc[i][0] = 0ull; acc[i][1] = 0ull; }

    for (int kt = 0; kt < DDIM; kt += BK) {
#pragma unroll
        for (int j = 0; j < 2; j++) {
            int idx = tid + j * 256;
            int row = idx >> 3;
            int c4  = (idx & 7) * 4;
            float4 va = *(const float4*)&x[(size_t)(gm + row) * DDIM + kt + c4];
            As[c4 + 0][row] = va.x; As[c4 + 1][row] = va.y;
            As[c4 + 2][row] = va.z; As[c4 + 3][row] = va.w;
            float4 vb = *(const float4*)&W[(size_t)(gn + row) * DDIM + kt + c4];
            Bs[c4 + 0][row] = vb.x; Bs[c4 + 1][row] = vb.y;
            Bs[c4 + 2][row] = vb.z; Bs[c4 + 3][row] = vb.w;
        }
        __syncthreads();
#pragma unroll
        for (int k = 0; k < BK; k++) {
            float4 av = *(const float4*)&As[k][m4];
            float4 bv = *(const float4*)&Bs[k][n4];
            unsigned long long bp0 = pk2(bv.x, bv.y);
            unsigned long long bp1 = pk2(bv.z, bv.w);
            unsigned long long aa;
            aa = pk2(av.x, av.x);
            acc[0][0] = fma2(aa, bp0, acc[0][0]); acc[0][1] = fma2(aa, bp1, acc[0][1]);
            aa = pk2(av.y, av.y);
            acc[1][0] = fma2(aa, bp0, acc[1][0]); acc[1][1] = fma2(aa, bp1, acc[1][1]);
            aa = pk2(av.z, av.z);
            acc[2][0] = fma2(aa, bp0, acc[2][0]); acc[2][1] = fma2(aa, bp1, acc[2][1]);
            aa = pk2(av.w, av.w);
            acc[3][0] = fma2(aa, bp0, acc[3][0]); acc[3][1] = fma2(aa, bp1, acc[3][1]);
        }
        __syncthreads();
    }

    float4 bb = *(const float4*)&bias[gn + n4];
#pragma unroll
    for (int mi = 0; mi < 4; mi++) {
        float o0, o1, o2, o3;
        upk2(acc[mi][0], o0, o1);
        upk2(acc[mi][1], o2, o3);
        float4 o = make_float4(o0 + bb.x, o1 + bb.y, o2 + bb.z, o3 + bb.w);
        *(float4*)&g_xg[(size_t)(gm + m4 + mi) * G3 + gn + n4] = o;
    }
}

// ---------------- Kernel 2: register-resident W, cluster-8 recurrence ----------------
// 16 clusters x 8 CTAs. Cluster owns 4 batches; CTA rank owns 32 h-indices
// (96 W_hh rows, held entirely in registers: 64 regs/lane).
// h exchanged per step via st.async -> mbarrier complete_tx on a 3-deep ring.
#define CLSZ 8
#define RTH  384
#define IDXC 32
#define NROW 96
#define BB   4

__device__ __forceinline__ float sigm_f(float x) { return 1.f / (1.f + __expf(-x)); }
__device__ __forceinline__ float tanh_f(float x) { return 1.f - 2.f / (__expf(2.f * x) + 1.f); }

__device__ __forceinline__ void st_async_b64(uint32_t laddr, uint32_t lmbar,
                                             uint32_t rk, unsigned long long v) {
    uint32_t ra, rm;
    asm volatile("mapa.shared::cluster.u32 %0, %1, %2;" : "=r"(ra) : "r"(laddr), "r"(rk));
    asm volatile("mapa.shared::cluster.u32 %0, %1, %2;" : "=r"(rm) : "r"(lmbar), "r"(rk));
    asm volatile("st.async.shared::cluster.mbarrier::complete_tx::bytes.b64 [%0], %1, [%2];"
                 :: "r"(ra), "l"(v), "r"(rm) : "memory");
}

__device__ __forceinline__ void mbar_wait_cluster(uint32_t mbar, uint32_t parity) {
    uint32_t done;
    asm volatile("{\n\t.reg .pred p;\n\t"
                 "mbarrier.try_wait.parity.acquire.cluster.shared::cta.b64 p, [%1], %2;\n\t"
                 "selp.b32 %0, 1, 0, p;\n\t}"
                 : "=r"(done) : "r"(mbar), "r"(parity) : "memory");
    while (!done) {
        asm volatile("{\n\t.reg .pred p;\n\t"
                     "mbarrier.try_wait.parity.acquire.cluster.shared::cta.b64 p, [%1], %2, 0x989680;\n\t"
                     "selp.b32 %0, 1, 0, p;\n\t}"
                     : "=r"(done) : "r"(mbar), "r"(parity) : "memory");
    }
}

__global__ __launch_bounds__(RTH, 1) void gru_rec(const float* __restrict__ h0,
                                                  const float* __restrict__ W_hh,
                                                  const float* __restrict__ b_hh,
                                                  float* __restrict__ hs,
                                                  float* __restrict__ hT) {
    __shared__ alignas(16) float sh_hring[3 * BB * HDIM];   // [slot][b][k]
    __shared__ alignas(16) float sh_hg[NROW * 4];           // [row][batch]
    __shared__ alignas(16) float sh_xgs[RTH];               // [b][g][il]
    __shared__ alignas(8)  unsigned long long sh_full[3];

    uint32_t rank; asm("mov.u32 %0, %%cluster_ctarank;" : "=r"(rank));
    const int tid = threadIdx.x;
    const int cb = (blockIdx.x >> 3) * BB;

    const uint32_t hring_s = (uint32_t)__cvta_generic_to_shared(sh_hring);
    const uint32_t full_s  = (uint32_t)__cvta_generic_to_shared(sh_full);

    // ---- load this lane's W slice into registers (64 regs as 32 packed pairs)
    const int w = tid >> 5, lane = tid & 31, rw = lane >> 2, kq = lane & 3;
    const int lr = w * 8 + rw, g = lr >> 5, il = lr & 31;
    const int grow = g * HDIM + (int)rank * IDXC + il;
    unsigned long long wq[32];
    {
        const ulonglong2* wp = (const ulonglong2*)(W_hh + (size_t)grow * HDIM + kq * 64);
#pragma unroll
        for (int j = 0; j < 16; j++) { ulonglong2 u = wp[j]; wq[2*j] = u.x; wq[2*j+1] = u.y; }
    }
    // ---- per-gate-thread biases
    float bhr = 0.f, bhz = 0.f, bhn = 0.f;
    if (tid < 128) {
        int gil = tid & 31, gi = (int)rank * IDXC + gil;
        bhr = b_hh[gi]; bhz = b_hh[HDIM + gi]; bhn = b_hh[2 * HDIM + gi];
    }
    // ---- h0 -> ring slot 0
    for (int i = tid; i < BB * HDIM; i += RTH) {
        int b = i >> 8, k = i & 255;
        sh_hring[i] = h0[(size_t)(cb + b) * HDIM + k];
    }
    if (tid == 0) {
#pragma unroll
        for (int s = 0; s < 3; s++)
            asm volatile("mbarrier.init.shared.b64 [%0], 1;" :: "r"(full_s + s * 8) : "memory");
        // arm slots 1 and 2 (filled by step-0 / step-1 writers); slot 0 re-armed at t=0
        asm volatile("mbarrier.arrive.expect_tx.shared.b64 _, [%0], %1;" :: "r"(full_s + 8),  "r"(4096u) : "memory");
        asm volatile("mbarrier.arrive.expect_tx.shared.b64 _, [%0], %1;" :: "r"(full_s + 16), "r"(4096u) : "memory");
    }
    __syncthreads();
    asm volatile("barrier.cluster.arrive.aligned;" ::: "memory");
    asm volatile("barrier.cluster.wait.aligned;" ::: "memory");

    // xg loader mapping: tid -> (batch, gate, idx)
    const int lb = tid / 96, rr = tid % 96;
    const size_t xg_base = ((size_t)(cb + lb) * TDIM) * G3
                         + (size_t)(rr >> 5) * HDIM + (size_t)rank * IDXC + (rr & 31);

    auto step = [&](int t, int slot, int slotN, int& par) {
        // prefetch xg for this step (DRAM latency hidden under wait+matvec)
        float xv = g_xg[xg_base + (size_t)t * G3];
        if (t > 0) {
            mbar_wait_cluster(full_s + slot * 8, (uint32_t)par);
            par ^= 1;
        }
        const float* hb = sh_hring + slot * (BB * HDIM);
        const ulonglong2* hp0 = (const ulonglong2*)(hb + 0 * HDIM + kq * 64);
        const ulonglong2* hp1 = (const ulonglong2*)(hb + 1 * HDIM + kq * 64);
        const ulonglong2* hp2 = (const ulonglong2*)(hb + 2 * HDIM + kq * 64);
        const ulonglong2* hp3 = (const ulonglong2*)(hb + 3 * HDIM + kq * 64);
        unsigned long long a0 = 0ull, a1 = 0ull, a2 = 0ull, a3 = 0ull;
#pragma unroll
        for (int c = 0; c < 16; c++) {
            ulonglong2 v0 = hp0[c]; a0 = fma2(wq[2*c], v0.x, a0); a0 = fma2(wq[2*c+1], v0.y, a0);
            ulonglong2 v1 = hp1[c]; a1 = fma2(wq[2*c], v1.x, a1); a1 = fma2(wq[2*c+1], v1.y, a1);
            ulonglong2 v2 = hp2[c]; a2 = fma2(wq[2*c], v2.x, a2); a2 = fma2(wq[2*c+1], v2.y, a2);
            ulonglong2 v3 = hp3[c]; a3 = fma2(wq[2*c], v3.x, a3); a3 = fma2(wq[2*c+1], v3.y, a3);
        }
        float s0, s1, s2, s3, xl, xh;
        upk2(a0, xl, xh); s0 = xl + xh;
        upk2(a1, xl, xh); s1 = xl + xh;
        upk2(a2, xl, xh); s2 = xl + xh;
        upk2(a3, xl, xh); s3 = xl + xh;
        s0 += __shfl_xor_sync(0xffffffffu, s0, 1); s0 += __shfl_xor_sync(0xffffffffu, s0, 2);
        s1 += __shfl_xor_sync(0xffffffffu, s1, 1); s1 += __shfl_xor_sync(0xffffffffu, s1, 2);
        s2 += __shfl_xor_sync(0xffffffffu, s2, 1); s2 += __shfl_xor_sync(0xffffffffu, s2, 2);
        s3 += __shfl_xor_sync(0xffffffffu, s3, 1); s3 += __shfl_xor_sync(0xffffffffu, s3, 2);
        // lane kq keeps batch kq; hg[row*4+batch] == hg[tid]
        float outv = (kq == 0) ? s0 : (kq == 1) ? s1 : (kq == 2) ? s2 : s3;
        sh_hg[tid] = outv;
        sh_xgs[tid] = xv;
        __syncthreads();
        if (tid == 0)  // re-arm this slot for its use at t+3
            asm volatile("mbarrier.arrive.expect_tx.shared.b64 _, [%0], %1;"
                         :: "r"(full_s + slot * 8), "r"(4096u) : "memory");
        if (tid < 128) {
            const int b = tid >> 5, gil = tid & 31;
            const int gi = (int)rank * IDXC + gil;
            float xr = sh_xgs[b * 96 + gil];
            float xz = sh_xgs[b * 96 + 32 + gil];
            float xn = sh_xgs[b * 96 + 64 + gil];
            float hr  = sh_hg[gil * 4 + b];
            float hz  = sh_hg[(32 + gil) * 4 + b];
            float hnv = sh_hg[(64 + gil) * 4 + b];
            float hprev = hb[b * HDIM + gi];
            float rg = sigm_f(xr + hr + bhr);
            float zg = sigm_f(xz + hz + bhz);
            float ng = tanh_f(xn + rg * (hnv + bhn));
            float hnew = (1.f - zg) * ng + zg * hprev;
            hs[((size_t)(cb + b) * TDIM + t) * HDIM + gi] = hnew;
            if (t == TDIM - 1) hT[(size_t)(cb + b) * HDIM + gi] = hnew;
            float hpart = __shfl_down_sync(0xffffffffu, hnew, 1);
            if (t < TDIM - 1 && (gil & 1) == 0) {
                unsigned long long pv = pk2(hnew, hpart);
                uint32_t laddr = hring_s + 4u * (uint32_t)(slotN * (BB * HDIM) + b * HDIM + gi);
                uint32_t lmbar = full_s + (uint32_t)slotN * 8u;
#pragma unroll
                for (uint32_t dr = 0; dr < CLSZ; dr++) st_async_b64(laddr, lmbar, dr, pv);
            }
        }
    };

    int p0 = 0, p1 = 0, p2 = 0;
    for (int tb = 0; tb < TDIM - 2; tb += 3) {
        step(tb + 0, 0, 1, p0);
        step(tb + 1, 1, 2, p1);
        step(tb + 2, 2, 0, p2);
    }
    step(TDIM - 2, 0, 1, p0);
    step(TDIM - 1, 1, 2, p1);

    asm volatile("barrier.cluster.arrive.aligned;" ::: "memory");
    asm volatile("barrier.cluster.wait.aligned;" ::: "memory");
}

// ---------------- launch ----------------
extern "C" void kernel_launch(void* const* d_in, const int* in_sizes, int n_in,
                              void* d_out, int out_size) {
    (void)in_sizes; (void)n_in; (void)out_size;
    const float* x    = (const float*)d_in[0];
    const float* h0   = (const float*)d_in[1];
    const float* W_ih = (const float*)d_in[2];
    const float* W_hh = (const float*)d_in[3];
    const float* b_ih = (const float*)d_in[4];
    const float* b_hh = (const float*)d_in[5];
    float* out = (float*)d_out;
    float* hs = out;
    float* hT = out + (size_t)BDIM * TDIM * HDIM;

    dim3 g1((BDIM * TDIM) / BM, G3 / BN);
    proj_gemm<<<g1, 256>>>(x, W_ih, b_ih);

    cudaLaunchConfig_t cfg = {};
    cfg.gridDim = dim3(16 * CLSZ, 1, 1);
    cfg.blockDim = dim3(RTH, 1, 1);
    cfg.dynamicSmemBytes = 0;
    cfg.stream = 0;
    cudaLaunchAttribute attrs[1];
    attrs[0].id = cudaLaunchAttributeClusterDimension;
    attrs[0].val.clusterDim.x = CLSZ;
    attrs[0].val.clusterDim.y = 1;
    attrs[0].val.clusterDim.z = 1;
    cfg.attrs = attrs;
    cfg.numAttrs = 1;
    cudaLaunchKernelEx(&cfg, gru_rec, h0, W_hh, b_hh, hs, hT);
}